// round 1
// baseline (speedup 1.0000x reference)
#include <cuda_runtime.h>

// Problem constants (fixed by the dataset)
#define KN_MAXN 10000
#define KN_MAXE 100000

// Scratch (no allocations allowed -> __device__ globals)
__device__ int g_counts[KN_MAXN];
__device__ int g_offsets[KN_MAXN + 1];
__device__ int g_cursor[KN_MAXN];
__device__ int g_sorted[KN_MAXE];

__device__ __forceinline__ int zmap(int z) {
    // ZS = [1,6,7,8,9] -> 0..4
    return (z == 1) ? 0 : (z - 5);
}

__global__ void k_zero(int N) {
    int i = blockIdx.x * blockDim.x + threadIdx.x;
    if (i < N) g_counts[i] = 0;
}

__global__ void k_hist(const int* __restrict__ recv, int E) {
    int e = blockIdx.x * blockDim.x + threadIdx.x;
    if (e < E) atomicAdd(&g_counts[recv[e]], 1);
}

// Single-block exclusive scan over counts -> offsets, cursor
__global__ void k_scan(int N) {
    __shared__ int sh[1024];
    __shared__ int s_carry;
    if (threadIdx.x == 0) s_carry = 0;
    __syncthreads();
    for (int base = 0; base < N; base += 1024) {
        int i = base + threadIdx.x;
        int v = (i < N) ? g_counts[i] : 0;
        sh[threadIdx.x] = v;
        __syncthreads();
        for (int off = 1; off < 1024; off <<= 1) {
            int t = (threadIdx.x >= off) ? sh[threadIdx.x - off] : 0;
            __syncthreads();
            sh[threadIdx.x] += t;
            __syncthreads();
        }
        int carry = s_carry;
        int excl = carry + sh[threadIdx.x] - v;
        if (i < N) { g_offsets[i] = excl; g_cursor[i] = excl; }
        __syncthreads();
        if (threadIdx.x == 0) s_carry = carry + sh[1023];
        __syncthreads();
    }
    if (threadIdx.x == 0) g_offsets[N] = s_carry;
}

__global__ void k_scatter(const int* __restrict__ recv, int E) {
    int e = blockIdx.x * blockDim.x + threadIdx.x;
    if (e < E) {
        int p = atomicAdd(&g_cursor[recv[e]], 1);
        g_sorted[p] = e;
    }
}

// Fused per-node kernel: one block per node, 160 threads = (l in 0..9, c in 0..15).
// Accumulates A_n[r,l,c] in registers (acc[8] per thread), contracts with W_rad,
// writes a0/a1/a2 directly.
__global__ __launch_bounds__(160) void k_node(
    const int* __restrict__ an, const int* __restrict__ e_send,
    const float* __restrict__ dij, const float* __restrict__ uij,
    const float* __restrict__ Wsend, const float* __restrict__ Wrecv,
    const float* __restrict__ widths, const float* __restrict__ Wrad,
    float* __restrict__ out, int N)
{
    const int n = blockIdx.x;
    const int tid = threadIdx.x;

    __shared__ float sWs[20];        // W_send table (5 x 4)
    __shared__ float sWrad[288];     // W_rad (3 x 8 x 12)
    __shared__ float sEmbR[4];       // this node's recv embedding
    __shared__ float sInv[8];        // 0.5 / widths^2
    __shared__ float sRad[32][8];
    __shared__ float sAng[32][10];
    __shared__ float sEnc[32][16];

    if (tid < 20) sWs[tid] = Wsend[tid];
    for (int i = tid; i < 288; i += 160) sWrad[i] = Wrad[i];
    if (tid < 8) { float w = widths[tid]; sInv[tid] = 0.5f / (w * w); }
    if (tid < 4) { int zi = zmap(an[n]); sEmbR[tid] = Wrecv[zi * 4 + tid]; }
    __syncthreads();

    const int lo = g_offsets[n];
    const int hi = g_offsets[n + 1];
    const int l = tid >> 4;
    const int c = tid & 15;

    float acc[8];
#pragma unroll
    for (int r = 0; r < 8; r++) acc[r] = 0.f;

    for (int base = lo; base < hi; base += 32) {
        int nb = min(32, hi - base);
        if (tid < nb) {
            int e = g_sorted[base + tid];
            float d = dij[e];
            float ux = uij[3 * e + 0], uy = uij[3 * e + 1], uz = uij[3 * e + 2];
            // polynomial cutoff, p=5: 1 - 21 x^5 + 35 x^6 - 15 x^7
            float xr = d * 0.25f;
            float x2 = xr * xr;
            float x4 = x2 * x2;
            float x5 = x4 * xr;
            float env = 1.f - 21.f * x5 + 35.f * x5 * xr - 15.f * x5 * x2;
            float rc = (d < 4.f) ? env : 0.f;
            float d2 = d * d;
#pragma unroll
            for (int r = 0; r < 8; r++)
                sRad[tid][r] = __expf(-d2 * sInv[r]) * rc;
            sAng[tid][0] = 1.f;
            sAng[tid][1] = ux; sAng[tid][2] = uy; sAng[tid][3] = uz;
            sAng[tid][4] = ux * ux; sAng[tid][5] = ux * uy; sAng[tid][6] = ux * uz;
            sAng[tid][7] = uy * uy; sAng[tid][8] = uy * uz; sAng[tid][9] = uz * uz;
            int zi = zmap(an[e_send[e]]);
#pragma unroll
            for (int i = 0; i < 4; i++) {
                float es = sWs[zi * 4 + i];
#pragma unroll
                for (int j = 0; j < 4; j++)
                    sEnc[tid][i * 4 + j] = es * sEmbR[j];
            }
        }
        __syncthreads();
        for (int e = 0; e < nb; e++) {
            float p = sAng[e][l] * sEnc[e][c];
#pragma unroll
            for (int r = 0; r < 8; r++)
                acc[r] = fmaf(sRad[e][r], p, acc[r]);
        }
        __syncthreads();
    }

    // einsum over r with W_rad[L_OF[l]]
    const int lg = (l == 0) ? 0 : ((l < 4) ? 1 : 2);
    const float* W = &sWrad[lg * 96];
    float val[12];
#pragma unroll
    for (int b = 0; b < 12; b++) val[b] = 0.f;
#pragma unroll
    for (int r = 0; r < 8; r++) {
        float a = acc[r];
#pragma unroll
        for (int b = 0; b < 12; b++)
            val[b] = fmaf(a, W[r * 12 + b], val[b]);
    }

    // Output layout: concat of raveled a0 (N,192), a1 (N,192,3), a2 (N,192,3,3).
    // feat index k = b*16 + c.
    if (l == 0) {
        float* p = out + (size_t)n * 192;
#pragma unroll
        for (int b = 0; b < 12; b++) p[b * 16 + c] = val[b];
    } else if (l < 4) {
        float* p = out + (size_t)N * 192 + (size_t)n * 576 + (l - 1);
#pragma unroll
        for (int b = 0; b < 12; b++) p[(size_t)(b * 16 + c) * 3] = val[b];
    } else {
        // symmetric 3x3 placement: ab4->(0,0); ab5->(0,1),(1,0); ab6->(0,2),(2,0);
        // ab7->(1,1); ab8->(1,2),(2,1); ab9->(2,2)
        const int P1[6] = {0, 1, 2, 4, 5, 8};
        const int P2[6] = {-1, 3, 6, -1, 7, -1};
        int li = l - 4;
        int o1 = P1[li], o2 = P2[li];
        float* p = out + (size_t)N * 768 + (size_t)n * 1728;
#pragma unroll
        for (int b = 0; b < 12; b++) {
            float v = val[b];
            int k9 = (b * 16 + c) * 9;
            p[k9 + o1] = v;
            if (o2 >= 0) p[k9 + o2] = v;
        }
    }
}

extern "C" void kernel_launch(void* const* d_in, const int* in_sizes, int n_in,
                              void* d_out, int out_size) {
    const int*   an     = (const int*)d_in[0];    // atomic_numbers (N)
    const int*   eidx   = (const int*)d_in[1];    // edge_index (2,E)
    const float* dij    = (const float*)d_in[2];  // (E)
    const float* uij    = (const float*)d_in[3];  // (E,3)
    // d_in[4] = positions (unused by reference math)
    const float* Wsend  = (const float*)d_in[5];  // (5,4)
    const float* Wrecv  = (const float*)d_in[6];  // (5,4)
    const float* widths = (const float*)d_in[7];  // (8)
    const float* Wrad   = (const float*)d_in[8];  // (3,8,12)
    float* out = (float*)d_out;

    int N = in_sizes[0];
    int E = in_sizes[2];
    const int* e_send = eidx;
    const int* e_recv = eidx + E;

    k_zero<<<(N + 255) / 256, 256>>>(N);
    k_hist<<<(E + 255) / 256, 256>>>(e_recv, E);
    k_scan<<<1, 1024>>>(N);
    k_scatter<<<(E + 255) / 256, 256>>>(e_recv, E);
    k_node<<<N, 160>>>(an, e_send, dij, uij, Wsend, Wrecv, widths, Wrad, out, N);
}

// round 2
// speedup vs baseline: 1.1140x; 1.1140x over previous
#include <cuda_runtime.h>

#define KN_MAXN 10000
#define KN_MAXE 100000

// Scratch (no allocations allowed -> __device__ globals, zero-initialized at load)
__device__ int g_counts[KN_MAXN];
__device__ int g_offsets[KN_MAXN + 1];
__device__ int g_cursor[KN_MAXN];
__device__ int g_sorted[KN_MAXE];

__device__ __forceinline__ int zmap(int z) {
    // ZS = [1,6,7,8,9] -> 0..4
    return (z == 1) ? 0 : (z - 5);
}

__global__ void k_hist(const int* __restrict__ recv, int E) {
    int e = blockIdx.x * blockDim.x + threadIdx.x;
    if (e < E) atomicAdd(&g_counts[recv[e]], 1);
}

// Single-block exclusive scan over counts -> offsets, cursor
__global__ void k_scan(int N) {
    __shared__ int sh[1024];
    __shared__ int s_carry;
    if (threadIdx.x == 0) s_carry = 0;
    __syncthreads();
    for (int base = 0; base < N; base += 1024) {
        int i = base + threadIdx.x;
        int v = (i < N) ? g_counts[i] : 0;
        sh[threadIdx.x] = v;
        __syncthreads();
        for (int off = 1; off < 1024; off <<= 1) {
            int t = (threadIdx.x >= off) ? sh[threadIdx.x - off] : 0;
            __syncthreads();
            sh[threadIdx.x] += t;
            __syncthreads();
        }
        int carry = s_carry;
        int excl = carry + sh[threadIdx.x] - v;
        if (i < N) { g_offsets[i] = excl; g_cursor[i] = excl; }
        __syncthreads();
        if (threadIdx.x == 0) s_carry = carry + sh[1023];
        __syncthreads();
    }
    if (threadIdx.x == 0) g_offsets[N] = s_carry;
}

__global__ void k_scatter(const int* __restrict__ recv, int E) {
    int e = blockIdx.x * blockDim.x + threadIdx.x;
    if (e < E) {
        int p = atomicAdd(&g_cursor[recv[e]], 1);
        g_sorted[p] = e;
    }
}

// Fused per-node kernel: one block per node, 160 threads = (l in 0..9, c in 0..15).
// Register accumulation of A_n[r,l,c], float4 shared reads, einsum with
// vectorized W_rad, outputs staged in shared then written coalesced.
__global__ __launch_bounds__(160) void k_node(
    const int* __restrict__ an, const int* __restrict__ e_send,
    const float* __restrict__ dij, const float* __restrict__ uij,
    const float* __restrict__ Wsend, const float* __restrict__ Wrecv,
    const float* __restrict__ widths, const float* __restrict__ Wrad,
    float* __restrict__ out, int N)
{
    const int n = blockIdx.x;
    const int tid = threadIdx.x;

    __shared__ float4 sWrad4[72];     // W_rad (3 x 8 x 12) as float4
    __shared__ float  sWs[20];        // W_send (5 x 4)
    __shared__ float  sEmbR[4];       // this node's recv embedding
    __shared__ float  sInv[8];        // 0.5 / widths^2
    __shared__ float4 sRad4[32][2];   // per-edge radial*cutoff (8 floats)
    __shared__ float  sAng[32][10];
    __shared__ float  sEnc[32][16];
    __shared__ float  sOut[2496];     // staged node output: a0|a1|a2

    if (tid == 0) g_counts[n] = 0;    // reset histogram for next replay
    if (tid < 20) sWs[tid] = Wsend[tid];
    if (tid >= 32 && tid < 104) sWrad4[tid - 32] = ((const float4*)Wrad)[tid - 32];
    if (tid < 8) { float w = widths[tid]; sInv[tid] = 0.5f / (w * w); }
    if (tid >= 28 && tid < 32) { int zi = zmap(an[n]); sEmbR[tid - 28] = Wrecv[zi * 4 + tid - 28]; }
    __syncthreads();

    const int lo = g_offsets[n];
    const int hi = g_offsets[n + 1];
    const int l = tid >> 4;
    const int c = tid & 15;

    float acc[8];
#pragma unroll
    for (int r = 0; r < 8; r++) acc[r] = 0.f;

    for (int base = lo; base < hi; base += 32) {
        int nb = min(32, hi - base);
        if (tid < nb) {
            int e = g_sorted[base + tid];
            float d = dij[e];
            float ux = uij[3 * e + 0], uy = uij[3 * e + 1], uz = uij[3 * e + 2];
            // polynomial cutoff, p=5: 1 - 21 x^5 + 35 x^6 - 15 x^7
            float xr = d * 0.25f;
            float x2 = xr * xr;
            float x5 = x2 * x2 * xr;
            float env = 1.f - 21.f * x5 + 35.f * x5 * xr - 15.f * x5 * x2;
            float rc = (d < 4.f) ? env : 0.f;
            float d2 = d * d;
            float rv[8];
#pragma unroll
            for (int r = 0; r < 8; r++)
                rv[r] = __expf(-d2 * sInv[r]) * rc;
            sRad4[tid][0] = make_float4(rv[0], rv[1], rv[2], rv[3]);
            sRad4[tid][1] = make_float4(rv[4], rv[5], rv[6], rv[7]);
            sAng[tid][0] = 1.f;
            sAng[tid][1] = ux; sAng[tid][2] = uy; sAng[tid][3] = uz;
            sAng[tid][4] = ux * ux; sAng[tid][5] = ux * uy; sAng[tid][6] = ux * uz;
            sAng[tid][7] = uy * uy; sAng[tid][8] = uy * uz; sAng[tid][9] = uz * uz;
            int zi = zmap(an[e_send[e]]);
#pragma unroll
            for (int i = 0; i < 4; i++) {
                float es = sWs[zi * 4 + i];
#pragma unroll
                for (int j = 0; j < 4; j++)
                    sEnc[tid][i * 4 + j] = es * sEmbR[j];
            }
        }
        __syncthreads();
        for (int e = 0; e < nb; e++) {
            float4 ra = sRad4[e][0];
            float4 rb = sRad4[e][1];
            float p = sAng[e][l] * sEnc[e][c];
            acc[0] = fmaf(ra.x, p, acc[0]);
            acc[1] = fmaf(ra.y, p, acc[1]);
            acc[2] = fmaf(ra.z, p, acc[2]);
            acc[3] = fmaf(ra.w, p, acc[3]);
            acc[4] = fmaf(rb.x, p, acc[4]);
            acc[5] = fmaf(rb.y, p, acc[5]);
            acc[6] = fmaf(rb.z, p, acc[6]);
            acc[7] = fmaf(rb.w, p, acc[7]);
        }
        __syncthreads();
    }

    // einsum over r with W_rad[L_OF[l]] (vectorized weight reads)
    const int lg = (l == 0) ? 0 : ((l < 4) ? 1 : 2);
    const float4* W4 = &sWrad4[lg * 24];
    float val[12];
#pragma unroll
    for (int b = 0; b < 12; b++) val[b] = 0.f;
#pragma unroll
    for (int r = 0; r < 8; r++) {
        float a = acc[r];
        float4 w0 = W4[r * 3 + 0];
        float4 w1 = W4[r * 3 + 1];
        float4 w2 = W4[r * 3 + 2];
        val[0] = fmaf(a, w0.x, val[0]);  val[1] = fmaf(a, w0.y, val[1]);
        val[2] = fmaf(a, w0.z, val[2]);  val[3] = fmaf(a, w0.w, val[3]);
        val[4] = fmaf(a, w1.x, val[4]);  val[5] = fmaf(a, w1.y, val[5]);
        val[6] = fmaf(a, w1.z, val[6]);  val[7] = fmaf(a, w1.w, val[7]);
        val[8] = fmaf(a, w2.x, val[8]);  val[9] = fmaf(a, w2.y, val[9]);
        val[10] = fmaf(a, w2.z, val[10]); val[11] = fmaf(a, w2.w, val[11]);
    }

    // Stage output in shared: sOut = [a0(192) | a1(576) | a2(1728)], then
    // write all three regions coalesced with float4.
    if (l == 0) {
#pragma unroll
        for (int b = 0; b < 12; b++) sOut[b * 16 + c] = val[b];
    } else if (l < 4) {
        float* p = sOut + 192 + (l - 1);
#pragma unroll
        for (int b = 0; b < 12; b++) p[(b * 16 + c) * 3] = val[b];
    } else {
        const int P1[6] = {0, 1, 2, 4, 5, 8};
        const int P2[6] = {-1, 3, 6, -1, 7, -1};
        int li = l - 4;
        int o1 = P1[li], o2 = P2[li];
        float* p = sOut + 768;
#pragma unroll
        for (int b = 0; b < 12; b++) {
            float v = val[b];
            int k9 = (b * 16 + c) * 9;
            p[k9 + o1] = v;
            if (o2 >= 0) p[k9 + o2] = v;
        }
    }
    __syncthreads();

    const float4* s4 = (const float4*)sOut;
    float4* g0 = (float4*)(out + (size_t)n * 192);
    float4* g1 = (float4*)(out + (size_t)N * 192 + (size_t)n * 576);
    float4* g2 = (float4*)(out + (size_t)N * 768 + (size_t)n * 1728);
    for (int i = tid; i < 624; i += 160) {
        float4 v = s4[i];
        if (i < 48)       g0[i]       = v;
        else if (i < 192) g1[i - 48]  = v;
        else              g2[i - 192] = v;
    }
}

extern "C" void kernel_launch(void* const* d_in, const int* in_sizes, int n_in,
                              void* d_out, int out_size) {
    const int*   an     = (const int*)d_in[0];    // atomic_numbers (N)
    const int*   eidx   = (const int*)d_in[1];    // edge_index (2,E)
    const float* dij    = (const float*)d_in[2];  // (E)
    const float* uij    = (const float*)d_in[3];  // (E,3)
    // d_in[4] = positions (unused by reference math)
    const float* Wsend  = (const float*)d_in[5];  // (5,4)
    const float* Wrecv  = (const float*)d_in[6];  // (5,4)
    const float* widths = (const float*)d_in[7];  // (8)
    const float* Wrad   = (const float*)d_in[8];  // (3,8,12)
    float* out = (float*)d_out;

    int N = in_sizes[0];
    int E = in_sizes[2];
    const int* e_send = eidx;
    const int* e_recv = eidx + E;

    // g_counts is zero on first call (static init) and re-zeroed by k_node
    // each call, so no k_zero launch is needed.
    k_hist<<<(E + 255) / 256, 256>>>(e_recv, E);
    k_scan<<<1, 1024>>>(N);
    k_scatter<<<(E + 255) / 256, 256>>>(e_recv, E);
    k_node<<<N, 160>>>(an, e_send, dij, uij, Wsend, Wrecv, widths, Wrad, out, N);
}

// round 3
// speedup vs baseline: 1.1176x; 1.0032x over previous
#include <cuda_runtime.h>

#define KN_MAXN 10000
#define KN_MAXE 100000

// Scratch (__device__ globals; zero-initialized at load)
__device__ int g_counts[KN_MAXN];
__device__ int g_offsets[KN_MAXN + 1];
__device__ int g_cursor[KN_MAXN];
// Per-edge record, written in recv-sorted order:
// floats [0:36) = R[lg=0..2][b=0..11], [36:46) ang, [46:48) pad, [48:64) enc
__device__ float4 g_edge[KN_MAXE * 16];

__device__ __forceinline__ int zmap(int z) {
    // ZS = [1,6,7,8,9] -> 0..4
    return (z == 1) ? 0 : (z - 5);
}

__global__ void k_hist(const int* __restrict__ recv, int E) {
    int e = blockIdx.x * blockDim.x + threadIdx.x;
    if (e < E) atomicAdd(&g_counts[recv[e]], 1);
}

// Single-pass block scan: 1024 threads, each owns a contiguous chunk.
__global__ void k_scan(int N) {
    __shared__ int warpsums[32];
    const int t = threadIdx.x;
    const int P = (N + 1023) >> 10;
    const int start = t * P;
    // local sum (pass 1)
    int s = 0;
    for (int k = 0; k < P; k++) {
        int i = start + k;
        if (i < N) s += g_counts[i];
    }
    // warp inclusive scan
    int lane = t & 31, wid = t >> 5;
    int x = s;
#pragma unroll
    for (int off = 1; off < 32; off <<= 1) {
        int y = __shfl_up_sync(0xffffffffu, x, off);
        if (lane >= off) x += y;
    }
    if (lane == 31) warpsums[wid] = x;
    __syncthreads();
    if (wid == 0) {
        int w = warpsums[lane];
#pragma unroll
        for (int off = 1; off < 32; off <<= 1) {
            int y = __shfl_up_sync(0xffffffffu, w, off);
            if (lane >= off) w += y;
        }
        warpsums[lane] = w;
    }
    __syncthreads();
    int run = x - s + (wid > 0 ? warpsums[wid - 1] : 0);  // exclusive prefix
    // pass 2: write offsets/cursor
    for (int k = 0; k < P; k++) {
        int i = start + k;
        if (i < N) {
            int v = g_counts[i];
            g_offsets[i] = run;
            g_cursor[i] = run;
            run += v;
        }
    }
    if (t == 1023) g_offsets[N] = run;
}

// Edge kernel: computes R (radial contracted with W_rad), angular, species
// encoding, and scatters the 64-float record into sorted position.
__global__ __launch_bounds__(256) void k_edge(
    const int* __restrict__ an, const int* __restrict__ e_send,
    const int* __restrict__ e_recv,
    const float* __restrict__ dij, const float* __restrict__ uij,
    const float* __restrict__ Wsend, const float* __restrict__ Wrecv,
    const float* __restrict__ widths, const float* __restrict__ Wrad, int E)
{
    __shared__ float4 sW4[72];   // W_rad (3 x 8 x 12)
    __shared__ float  sWs[20];   // W_send
    __shared__ float  sWr[20];   // W_recv
    __shared__ float  sInv[8];   // 0.5/width^2

    const int tid = threadIdx.x;
    if (tid < 72) sW4[tid] = ((const float4*)Wrad)[tid];
    if (tid >= 72 && tid < 92) sWs[tid - 72] = Wsend[tid - 72];
    if (tid >= 92 && tid < 112) sWr[tid - 92] = Wrecv[tid - 92];
    if (tid >= 112 && tid < 120) { float w = widths[tid - 112]; sInv[tid - 112] = 0.5f / (w * w); }
    __syncthreads();

    const int e = blockIdx.x * 256 + tid;
    if (e >= E) return;

    const float d = dij[e];
    const float ux = uij[3 * e + 0], uy = uij[3 * e + 1], uz = uij[3 * e + 2];
    // cutoff p=5: 1 - 21 x^5 + 35 x^6 - 15 x^7
    float xr = d * 0.25f;
    float x2 = xr * xr;
    float x5 = x2 * x2 * xr;
    float env = 1.f - 21.f * x5 + 35.f * x5 * xr - 15.f * x5 * x2;
    float rc = (d < 4.f) ? env : 0.f;
    float d2 = d * d;
    float rad[8];
#pragma unroll
    for (int r = 0; r < 8; r++) rad[r] = __expf(-d2 * sInv[r]) * rc;

    const int recv = e_recv[e];
    const int p = atomicAdd(&g_cursor[recv], 1);
    float4* dst = g_edge + (size_t)p * 16;

    // R rows: R[lg][b] = sum_r rad[r] * W[lg][r][b]
#pragma unroll
    for (int lg = 0; lg < 3; lg++) {
        float o[12];
#pragma unroll
        for (int b = 0; b < 12; b++) o[b] = 0.f;
#pragma unroll
        for (int r = 0; r < 8; r++) {
            float a = rad[r];
            float4 w0 = sW4[lg * 24 + r * 3 + 0];
            float4 w1 = sW4[lg * 24 + r * 3 + 1];
            float4 w2 = sW4[lg * 24 + r * 3 + 2];
            o[0]  = fmaf(a, w0.x, o[0]);  o[1]  = fmaf(a, w0.y, o[1]);
            o[2]  = fmaf(a, w0.z, o[2]);  o[3]  = fmaf(a, w0.w, o[3]);
            o[4]  = fmaf(a, w1.x, o[4]);  o[5]  = fmaf(a, w1.y, o[5]);
            o[6]  = fmaf(a, w1.z, o[6]);  o[7]  = fmaf(a, w1.w, o[7]);
            o[8]  = fmaf(a, w2.x, o[8]);  o[9]  = fmaf(a, w2.y, o[9]);
            o[10] = fmaf(a, w2.z, o[10]); o[11] = fmaf(a, w2.w, o[11]);
        }
        dst[lg * 3 + 0] = make_float4(o[0], o[1], o[2], o[3]);
        dst[lg * 3 + 1] = make_float4(o[4], o[5], o[6], o[7]);
        dst[lg * 3 + 2] = make_float4(o[8], o[9], o[10], o[11]);
    }
    // angular [1,x,y,z,xx,xy,xz,yy,yz,zz] at floats 36..45
    dst[9]  = make_float4(1.f, ux, uy, uz);
    dst[10] = make_float4(ux * ux, ux * uy, ux * uz, uy * uy);
    dst[11] = make_float4(uy * uz, uz * uz, 0.f, 0.f);
    // enc at floats 48..63
    const int zs = zmap(an[e_send[e]]);
    const int zr = zmap(recv >= 0 ? an[recv] : 0);
    float er0 = sWr[zr * 4 + 0], er1 = sWr[zr * 4 + 1];
    float er2 = sWr[zr * 4 + 2], er3 = sWr[zr * 4 + 3];
#pragma unroll
    for (int i = 0; i < 4; i++) {
        float es = sWs[zs * 4 + i];
        dst[12 + i] = make_float4(es * er0, es * er1, es * er2, es * er3);
    }
}

// Node kernel: one block per node, 160 threads = (l in 0..9, c in 0..15).
// acc[12] registers ARE the output features; no einsum needed.
__global__ __launch_bounds__(160) void k_node(float* __restrict__ out, int N)
{
    const int n = blockIdx.x;
    const int tid = threadIdx.x;

    __shared__ float4 sBuf4[624];           // 2496 floats: edge staging / output staging
    float* sBuf = (float*)sBuf4;

    if (tid == 0) g_counts[n] = 0;          // reset histogram for next replay

    const int lo = g_offsets[n];
    const int hi = g_offsets[n + 1];
    const int l = tid >> 4;
    const int c = tid & 15;
    const int lg3 = ((l == 0) ? 0 : ((l < 4) ? 1 : 2)) * 3;
    const int aOff = 36 + l;
    const int eOff = 48 + c;

    float acc[12];
#pragma unroll
    for (int b = 0; b < 12; b++) acc[b] = 0.f;

    for (int base = lo; base < hi; base += 32) {
        const int nb = min(32, hi - base);
        const int cnt4 = nb * 16;
        const float4* src = g_edge + (size_t)base * 16;
        for (int i = tid; i < cnt4; i += 160) sBuf4[i] = src[i];
        __syncthreads();
        const float* ep = sBuf;
        for (int j = 0; j < nb; j++, ep += 64) {
            float p = ep[aOff] * ep[eOff];
            const float4* R4 = (const float4*)ep + lg3;
            float4 r0 = R4[0], r1 = R4[1], r2 = R4[2];
            acc[0]  = fmaf(r0.x, p, acc[0]);  acc[1]  = fmaf(r0.y, p, acc[1]);
            acc[2]  = fmaf(r0.z, p, acc[2]);  acc[3]  = fmaf(r0.w, p, acc[3]);
            acc[4]  = fmaf(r1.x, p, acc[4]);  acc[5]  = fmaf(r1.y, p, acc[5]);
            acc[6]  = fmaf(r1.z, p, acc[6]);  acc[7]  = fmaf(r1.w, p, acc[7]);
            acc[8]  = fmaf(r2.x, p, acc[8]);  acc[9]  = fmaf(r2.y, p, acc[9]);
            acc[10] = fmaf(r2.z, p, acc[10]); acc[11] = fmaf(r2.w, p, acc[11]);
        }
        __syncthreads();
    }

    // Stage output in shared: [a0(192) | a1(576) | a2(1728)], write coalesced.
    if (l == 0) {
#pragma unroll
        for (int b = 0; b < 12; b++) sBuf[b * 16 + c] = acc[b];
    } else if (l < 4) {
        float* p = sBuf + 192 + (l - 1);
#pragma unroll
        for (int b = 0; b < 12; b++) p[(b * 16 + c) * 3] = acc[b];
    } else {
        const int P1[6] = {0, 1, 2, 4, 5, 8};
        const int P2[6] = {-1, 3, 6, -1, 7, -1};
        int li = l - 4;
        int o1 = P1[li], o2 = P2[li];
        float* p = sBuf + 768;
#pragma unroll
        for (int b = 0; b < 12; b++) {
            float v = acc[b];
            int k9 = (b * 16 + c) * 9;
            p[k9 + o1] = v;
            if (o2 >= 0) p[k9 + o2] = v;
        }
    }
    __syncthreads();

    float4* g0 = (float4*)(out + (size_t)n * 192);
    float4* g1 = (float4*)(out + (size_t)N * 192 + (size_t)n * 576);
    float4* g2 = (float4*)(out + (size_t)N * 768 + (size_t)n * 1728);
    for (int i = tid; i < 624; i += 160) {
        float4 v = sBuf4[i];
        if (i < 48)       g0[i]       = v;
        else if (i < 192) g1[i - 48]  = v;
        else              g2[i - 192] = v;
    }
}

extern "C" void kernel_launch(void* const* d_in, const int* in_sizes, int n_in,
                              void* d_out, int out_size) {
    const int*   an     = (const int*)d_in[0];    // atomic_numbers (N)
    const int*   eidx   = (const int*)d_in[1];    // edge_index (2,E)
    const float* dij    = (const float*)d_in[2];  // (E)
    const float* uij    = (const float*)d_in[3];  // (E,3)
    // d_in[4] = positions (unused by reference math)
    const float* Wsend  = (const float*)d_in[5];  // (5,4)
    const float* Wrecv  = (const float*)d_in[6];  // (5,4)
    const float* widths = (const float*)d_in[7];  // (8)
    const float* Wrad   = (const float*)d_in[8];  // (3,8,12)
    float* out = (float*)d_out;

    int N = in_sizes[0];
    int E = in_sizes[2];
    const int* e_send = eidx;
    const int* e_recv = eidx + E;

    // g_counts: zero at load, re-zeroed each call by k_node.
    k_hist<<<(E + 255) / 256, 256>>>(e_recv, E);
    k_scan<<<1, 1024>>>(N);
    k_edge<<<(E + 255) / 256, 256>>>(an, e_send, e_recv, dij, uij,
                                     Wsend, Wrecv, widths, Wrad, E);
    k_node<<<N, 160>>>(out, N);
}